// round 2
// baseline (speedup 1.0000x reference)
#include <cuda_runtime.h>
#include <cstdint>

#define NG 2500
#define NT 20000
#define NE 640000
#define SRCD 128
#define DSTD 500
#define HID 128
#define OUTD 128
#define NCLS 16

// ---------------- scratch (device globals; no allocation allowed) ----------------
__device__ int   g_cnt[NT];
__device__ int   g_rowstart[NT];
__device__ int   g_cursor[NT];
__device__ int   g_sorted[NE];
__device__ float g_agg[(size_t)NT * HID];
__device__ float g_h1 [(size_t)NT * HID];
__device__ float g_h2 [(size_t)NT * OUTD];
__device__ float g_t  [(size_t)NT * OUTD];

// ---------------- packed f32x2 helpers ----------------
__device__ __forceinline__ uint64_t pack2(float x, float y) {
    uint64_t r;
    asm("mov.b64 %0, {%1, %2};" : "=l"(r) : "f"(x), "f"(y));
    return r;
}
__device__ __forceinline__ uint64_t fma2(uint64_t a, uint64_t b, uint64_t c) {
    uint64_t d;
    asm("fma.rn.f32x2 %0, %1, %2, %3;" : "=l"(d) : "l"(a), "l"(b), "l"(c));
    return d;
}
__device__ __forceinline__ float2 unpack2(uint64_t v) {
    float2 f;
    asm("mov.b64 {%0, %1}, %2;" : "=f"(f.x), "=f"(f.y) : "l"(v));
    return f;
}

// ---------------- 1) zero counters ----------------
__global__ void zero_kernel() {
    int i = blockIdx.x * blockDim.x + threadIdx.x;
    if (i < NT) { g_cnt[i] = 0; g_cursor[i] = 0; }
}

// ---------------- 2) histogram of edge_dst ----------------
__global__ void hist_kernel(const int* __restrict__ edst) {
    int e = blockIdx.x * blockDim.x + threadIdx.x;
    if (e < NE) atomicAdd(&g_cnt[edst[e]], 1);
}

// ---------------- 3) exclusive scan over 20000 bins (single block) ----------------
__global__ void scan_kernel() {
    __shared__ int sh[1024];
    __shared__ int s_off;
    if (threadIdx.x == 0) s_off = 0;
    __syncthreads();
    for (int base = 0; base < NT; base += 1024) {
        int i = base + threadIdx.x;
        int v = (i < NT) ? g_cnt[i] : 0;
        sh[threadIdx.x] = v;
        __syncthreads();
        #pragma unroll
        for (int d = 1; d < 1024; d <<= 1) {
            int t = (threadIdx.x >= d) ? sh[threadIdx.x - d] : 0;
            __syncthreads();
            sh[threadIdx.x] += t;
            __syncthreads();
        }
        int incl = sh[threadIdx.x];
        if (i < NT) g_rowstart[i] = s_off + incl - v;   // exclusive prefix
        __syncthreads();
        if (threadIdx.x == 1023) s_off += incl;         // chunk total
        __syncthreads();
    }
}

// ---------------- 4) scatter edge_src into CSR order ----------------
__global__ void scatter_kernel(const int* __restrict__ esrc,
                               const int* __restrict__ edst) {
    int e = blockIdx.x * blockDim.x + threadIdx.x;
    if (e < NE) {
        int d = edst[e];
        int pos = atomicAdd(&g_cursor[d], 1);
        g_sorted[g_rowstart[d] + pos] = esrc[e];
    }
}

// ---------------- 5) gather-style mean aggregation: one warp per dst ----------------
__global__ void agg_kernel(const float* __restrict__ gene) {
    int d = blockIdx.x * 8 + (threadIdx.x >> 5);
    if (d >= NT) return;
    int lane = threadIdx.x & 31;

    int start = g_rowstart[d];
    int n     = g_cnt[d];

    const float4* G = reinterpret_cast<const float4*>(gene);

    float4 a0 = {0.f,0.f,0.f,0.f}, a1 = a0, a2 = a0, a3 = a0;
    int e = 0;
    for (; e + 4 <= n; e += 4) {
        int s0 = g_sorted[start + e + 0];
        int s1 = g_sorted[start + e + 1];
        int s2 = g_sorted[start + e + 2];
        int s3 = g_sorted[start + e + 3];
        float4 v0 = G[s0 * 32 + lane];
        float4 v1 = G[s1 * 32 + lane];
        float4 v2 = G[s2 * 32 + lane];
        float4 v3 = G[s3 * 32 + lane];
        a0.x += v0.x; a0.y += v0.y; a0.z += v0.z; a0.w += v0.w;
        a1.x += v1.x; a1.y += v1.y; a1.z += v1.z; a1.w += v1.w;
        a2.x += v2.x; a2.y += v2.y; a2.z += v2.z; a2.w += v2.w;
        a3.x += v3.x; a3.y += v3.y; a3.z += v3.z; a3.w += v3.w;
    }
    for (; e < n; e++) {
        int s = g_sorted[start + e];
        float4 v = G[s * 32 + lane];
        a0.x += v.x; a0.y += v.y; a0.z += v.z; a0.w += v.w;
    }
    float4 acc;
    acc.x = a0.x + a1.x + a2.x + a3.x;
    acc.y = a0.y + a1.y + a2.y + a3.y;
    acc.z = a0.z + a1.z + a2.z + a3.z;
    acc.w = a0.w + a1.w + a2.w + a3.w;

    float inv = 1.0f / fmaxf((float)n, 1.0f);
    acc.x *= inv; acc.y *= inv; acc.z *= inv; acc.w *= inv;
    reinterpret_cast<float4*>(g_agg)[(size_t)d * 32 + lane] = acc;
}

// ---------------- 6) dual-input tiled GEMM: C = act(A1@B1 + A2@B2 + bias) ----------------
// N fixed = 128. BM=64, BK=16, 256 threads, each thread 4 rows x 8 cols (4x4 f32x2).
__global__ __launch_bounds__(256)
void gemm_dual_kernel(const float* __restrict__ A1, int lda1, int K1,
                      const float* __restrict__ B1,
                      const float* __restrict__ A2, int lda2, int K2,
                      const float* __restrict__ B2,
                      const float* __restrict__ bias,
                      float* __restrict__ C, int M, int do_relu) {
    __shared__ float As[16][68];   // padded: conflict-light stores, float4-aligned rows
    __shared__ float Bs[16][128];

    int tid = threadIdx.x;
    int tx = tid & 15;             // col group: cols tx*8 .. tx*8+7
    int ty = tid >> 4;             // row group: rows ty*4 .. ty*4+3
    int row0 = blockIdx.x * 64;

    uint64_t acc[4][4];
    #pragma unroll
    for (int i = 0; i < 4; i++)
        #pragma unroll
        for (int j = 0; j < 4; j++) acc[i][j] = 0ull;

    const float* Aarr[2] = {A1, A2};
    const float* Barr[2] = {B1, B2};
    int ldas[2] = {lda1, lda2};
    int Ks[2]   = {K1, K2};

    for (int p = 0; p < 2; p++) {
        const float* A = Aarr[p];
        const float* B = Barr[p];
        int lda = ldas[p];
        int K   = Ks[p];
        if (K == 0) continue;

        for (int k0 = 0; k0 < K; k0 += 16) {
            // load A tile 64x16 (coalesced along k), store transposed As[k][r]
            #pragma unroll
            for (int i = 0; i < 4; i++) {
                int idx = tid + i * 256;
                int r = idx >> 4, k = idx & 15;
                int gr = row0 + r, gk = k0 + k;
                float v = 0.f;
                if (gr < M && gk < K) v = A[(size_t)gr * lda + gk];
                As[k][r] = v;
            }
            // load B tile 16x128 (coalesced along n)
            #pragma unroll
            for (int i = 0; i < 8; i++) {
                int idx = tid + i * 256;
                int k = idx >> 7, n = idx & 127;
                int gk = k0 + k;
                Bs[k][n] = (gk < K) ? B[(size_t)gk * 128 + n] : 0.f;
            }
            __syncthreads();

            #pragma unroll
            for (int kk = 0; kk < 16; kk++) {
                float4 a4 = *reinterpret_cast<const float4*>(&As[kk][ty * 4]);
                const ulonglong2* bp =
                    reinterpret_cast<const ulonglong2*>(&Bs[kk][tx * 8]);
                ulonglong2 bA = bp[0], bB = bp[1];
                uint64_t bb[4] = {bA.x, bA.y, bB.x, bB.y};
                uint64_t aa[4] = {pack2(a4.x, a4.x), pack2(a4.y, a4.y),
                                  pack2(a4.z, a4.z), pack2(a4.w, a4.w)};
                #pragma unroll
                for (int i = 0; i < 4; i++)
                    #pragma unroll
                    for (int j = 0; j < 4; j++)
                        acc[i][j] = fma2(aa[i], bb[j], acc[i][j]);
            }
            __syncthreads();
        }
    }

    // epilogue: bias + relu + store
    #pragma unroll
    for (int i = 0; i < 4; i++) {
        int r = row0 + ty * 4 + i;
        if (r >= M) continue;
        float* crow = C + (size_t)r * 128 + tx * 8;
        #pragma unroll
        for (int j = 0; j < 4; j++) {
            float2 v = unpack2(acc[i][j]);
            int c = tx * 8 + j * 2;
            v.x += bias[c];
            v.y += bias[c + 1];
            if (do_relu) { v.x = fmaxf(v.x, 0.f); v.y = fmaxf(v.y, 0.f); }
            *reinterpret_cast<float2*>(crow + j * 2) = v;
        }
    }
}

// ---------------- 7) classifier tail: out[NT,16] = T[NT,128] @ Wc2[128,16] + bc2 ----------------
__global__ __launch_bounds__(256)
void cls_kernel(const float* __restrict__ T, const float* __restrict__ W,
                const float* __restrict__ b, float* __restrict__ out) {
    __shared__ float sW[HID * NCLS];
    __shared__ float sb[NCLS];
    for (int i = threadIdx.x; i < HID * NCLS; i += 256) sW[i] = W[i];
    if (threadIdx.x < NCLS) sb[threadIdx.x] = b[threadIdx.x];
    __syncthreads();

    int row = blockIdx.x * 16 + (threadIdx.x >> 4);
    int col = threadIdx.x & 15;
    if (row >= NT) return;

    float s = sb[col];
    const float4* tp = reinterpret_cast<const float4*>(T + (size_t)row * HID);
    #pragma unroll 8
    for (int k4 = 0; k4 < 32; k4++) {
        float4 v = tp[k4];
        int k = k4 * 4;
        s = fmaf(v.x, sW[(k + 0) * NCLS + col], s);
        s = fmaf(v.y, sW[(k + 1) * NCLS + col], s);
        s = fmaf(v.z, sW[(k + 2) * NCLS + col], s);
        s = fmaf(v.w, sW[(k + 3) * NCLS + col], s);
    }
    out[(size_t)row * NCLS + col] = s;
}

// ---------------- launcher ----------------
extern "C" void kernel_launch(void* const* d_in, const int* in_sizes, int n_in,
                              void* d_out, int out_size) {
    const float* gene  = (const float*)d_in[0];
    const float* train = (const float*)d_in[1];
    const int*   esrc  = (const int*)d_in[2];
    const int*   edst  = (const int*)d_in[3];
    const float* W1n   = (const float*)d_in[4];
    const float* W1s   = (const float*)d_in[5];
    const float* b1    = (const float*)d_in[6];
    const float* W2n   = (const float*)d_in[7];
    const float* W2s   = (const float*)d_in[8];
    const float* b2    = (const float*)d_in[9];
    const float* Wc1   = (const float*)d_in[10];
    const float* bc1   = (const float*)d_in[11];
    const float* Wc2   = (const float*)d_in[12];
    const float* bc2   = (const float*)d_in[13];
    float* out = (float*)d_out;

    float* agg = nullptr; float* h1 = nullptr; float* h2 = nullptr; float* t = nullptr;
    cudaGetSymbolAddress((void**)&agg, g_agg);
    cudaGetSymbolAddress((void**)&h1,  g_h1);
    cudaGetSymbolAddress((void**)&h2,  g_h2);
    cudaGetSymbolAddress((void**)&t,   g_t);

    zero_kernel<<<(NT + 255) / 256, 256>>>();
    hist_kernel<<<(NE + 255) / 256, 256>>>(edst);
    scan_kernel<<<1, 1024>>>();
    scatter_kernel<<<(NE + 255) / 256, 256>>>(esrc, edst);
    agg_kernel<<<(NT + 7) / 8, 256>>>(gene);

    int gblk = (NT + 63) / 64;  // 313
    // h1 = relu(train @ W1_self + agg @ W1_neigh + b1)
    gemm_dual_kernel<<<gblk, 256>>>(train, DSTD, DSTD, W1s,
                                    agg, HID, HID, W1n, b1, h1, NT, 1);
    // h2 = relu(h1 @ W2_self + agg @ W2_neigh + b2)
    gemm_dual_kernel<<<gblk, 256>>>(h1, HID, HID, W2s,
                                    agg, HID, HID, W2n, b2, h2, NT, 1);
    // t = relu(h2 @ Wc1 + bc1)
    gemm_dual_kernel<<<gblk, 256>>>(h2, OUTD, OUTD, Wc1,
                                    nullptr, 0, 0, nullptr, bc1, t, NT, 1);
    // out = t @ Wc2 + bc2
    cls_kernel<<<(NT + 15) / 16, 256>>>(t, Wc2, bc2, out);
}

// round 7
// speedup vs baseline: 2.3858x; 2.3858x over previous
#include <cuda_runtime.h>
#include <cstdint>

#define NG 2500
#define NT 20000
#define NE 640000
#define SRCD 128
#define DSTD 500
#define HID 128
#define OUTD 128
#define NCLS 16

// ---------------- scratch (device globals; no allocation allowed) ----------------
__device__ int   g_cnt[NT];
__device__ int   g_rowstart[NT];
__device__ int   g_pos[NE];
__device__ int   g_sorted[NE];
__device__ float g_agg[(size_t)NT * HID];
__device__ float g_h1 [(size_t)NT * HID];
__device__ float g_h2 [(size_t)NT * OUTD];
__device__ float g_t  [(size_t)NT * OUTD];
// transposed weights, [N=128, Kpad] K-major, zero-padded
__device__ float g_Bt1s[128 * 512];
__device__ float g_Bt1n[128 * 128];
__device__ float g_Bt2s[128 * 128];
__device__ float g_Bt2n[128 * 128];
__device__ float g_Btc1[128 * 128];

__device__ __forceinline__ uint32_t f2tf32(float f) {
    uint32_t u;
    asm("cvt.rna.tf32.f32 %0, %1;" : "=r"(u) : "f"(f));
    return u;
}

// ---------------- 1) zero counters ----------------
__global__ void zero_kernel() {
    int i = blockIdx.x * blockDim.x + threadIdx.x;
    if (i < NT) g_cnt[i] = 0;
}

// ---------------- 2) histogram + within-row rank ----------------
__global__ void hist_kernel(const int* __restrict__ edst) {
    int e = blockIdx.x * blockDim.x + threadIdx.x;
    if (e < NE) g_pos[e] = atomicAdd(&g_cnt[edst[e]], 1);
}

// ---------------- 3) exclusive scan, shuffle-based, 1 block ----------------
__global__ __launch_bounds__(1024) void scan_kernel() {
    __shared__ int wsum[32];
    int t = threadIdx.x, lane = t & 31, w = t >> 5;
    const int L = 20;                         // 1000 threads x 20 = 20000
    int local[L];
    int s = 0;
    if (t < 1000) {
        int base = t * L;
        #pragma unroll
        for (int j = 0; j < L; j++) { local[j] = s; s += g_cnt[base + j]; }
    }
    int incl = s;
    #pragma unroll
    for (int d = 1; d < 32; d <<= 1) {
        int x = __shfl_up_sync(0xFFFFFFFFu, incl, d);
        if (lane >= d) incl += x;
    }
    if (lane == 31) wsum[w] = incl;
    __syncthreads();
    if (w == 0) {
        int v = wsum[lane];
        #pragma unroll
        for (int d = 1; d < 32; d <<= 1) {
            int x = __shfl_up_sync(0xFFFFFFFFu, v, d);
            if (lane >= d) v += x;
        }
        wsum[lane] = v;
    }
    __syncthreads();
    int off = (w > 0 ? wsum[w - 1] : 0) + incl - s;   // exclusive thread offset
    if (t < 1000) {
        int base = t * L;
        #pragma unroll
        for (int j = 0; j < L; j++) g_rowstart[base + j] = off + local[j];
    }
}

// ---------------- 4) pure scatter (no atomics) ----------------
__global__ void scatter_kernel(const int* __restrict__ esrc, const int* __restrict__ edst) {
    int e = blockIdx.x * blockDim.x + threadIdx.x;
    if (e < NE) g_sorted[g_rowstart[edst[e]] + g_pos[e]] = esrc[e];
}

// ---------------- 5) gather-style mean aggregation: one warp per dst ----------------
__global__ void agg_kernel(const float* __restrict__ gene) {
    int d = blockIdx.x * 8 + (threadIdx.x >> 5);
    if (d >= NT) return;
    int lane = threadIdx.x & 31;
    int start = g_rowstart[d];
    int n = g_cnt[d];
    const float4* G = reinterpret_cast<const float4*>(gene);

    float4 a0 = {0.f, 0.f, 0.f, 0.f}, a1 = a0, a2 = a0, a3 = a0;
    int e = 0;
    for (; e + 4 <= n; e += 4) {
        int s0 = g_sorted[start + e + 0];
        int s1 = g_sorted[start + e + 1];
        int s2 = g_sorted[start + e + 2];
        int s3 = g_sorted[start + e + 3];
        float4 v0 = G[s0 * 32 + lane];
        float4 v1 = G[s1 * 32 + lane];
        float4 v2 = G[s2 * 32 + lane];
        float4 v3 = G[s3 * 32 + lane];
        a0.x += v0.x; a0.y += v0.y; a0.z += v0.z; a0.w += v0.w;
        a1.x += v1.x; a1.y += v1.y; a1.z += v1.z; a1.w += v1.w;
        a2.x += v2.x; a2.y += v2.y; a2.z += v2.z; a2.w += v2.w;
        a3.x += v3.x; a3.y += v3.y; a3.z += v3.z; a3.w += v3.w;
    }
    for (; e < n; e++) {
        int s = g_sorted[start + e];
        float4 v = G[s * 32 + lane];
        a0.x += v.x; a0.y += v.y; a0.z += v.z; a0.w += v.w;
    }
    float4 acc;
    acc.x = a0.x + a1.x + a2.x + a3.x;
    acc.y = a0.y + a1.y + a2.y + a3.y;
    acc.z = a0.z + a1.z + a2.z + a3.z;
    acc.w = a0.w + a1.w + a2.w + a3.w;
    float inv = 1.0f / fmaxf((float)n, 1.0f);
    acc.x *= inv; acc.y *= inv; acc.z *= inv; acc.w *= inv;
    reinterpret_cast<float4*>(g_agg)[(size_t)d * 32 + lane] = acc;
}

// ---------------- 6) weight transpose: [K,128] -> [128,Kpad] K-major, zero-padded --------
__global__ void transw_kernel(const float* __restrict__ W1s, const float* __restrict__ W1n,
                              const float* __restrict__ W2s, const float* __restrict__ W2n,
                              const float* __restrict__ Wc1) {
    int m = blockIdx.y;
    const float* src; float* dst; int K, Kpad;
    if      (m == 0) { src = W1s; dst = g_Bt1s; K = DSTD; Kpad = 512; }
    else if (m == 1) { src = W1n; dst = g_Bt1n; K = HID;  Kpad = 128; }
    else if (m == 2) { src = W2s; dst = g_Bt2s; K = HID;  Kpad = 128; }
    else if (m == 3) { src = W2n; dst = g_Bt2n; K = HID;  Kpad = 128; }
    else             { src = Wc1; dst = g_Btc1; K = OUTD; Kpad = 128; }
    int i = blockIdx.x * 256 + threadIdx.x;
    if (i < 128 * Kpad) {
        int n = i / Kpad, k = i % Kpad;
        dst[i] = (k < K) ? src[k * 128 + n] : 0.f;
    }
}

// ---------------- 7) mma.sync tf32 dual GEMM: C = act(A1@B1 + A2@B2 + bias) --------------
// Block tile 128x128, 8 warps (4 along M x 2 along N), warp tile 32x64.
// mma.m16n8k8.row.col tf32: per warp per k8-step: 2 A-frags x 8 B-frags = 16 mma.
#define KC   32            // k-chunk (floats)
#define KPADS 36           // smem row stride (pad 4)

__global__ __launch_bounds__(256, 2)
void mma_gemm_dual(const float* __restrict__ A1, int lda1, int K1, const float* __restrict__ Bt1, int kpad1,
                   const float* __restrict__ A2, int lda2, int K2, const float* __restrict__ Bt2, int kpad2,
                   const float* __restrict__ bias, float* __restrict__ C, int M, int do_relu) {
    __shared__ uint32_t As[128 * KPADS];
    __shared__ uint32_t Bs[128 * KPADS];
    __shared__ float sbias[128];

    int tid = threadIdx.x;
    int wid = tid >> 5, lane = tid & 31;
    int wm = wid & 3, wn = wid >> 2;       // warp row/col in 4x2 grid
    int g  = lane >> 2, tq = lane & 3;     // fragment group / quad
    int row0 = blockIdx.x * 128;

    if (tid < 128) sbias[tid] = bias[tid];

    float acc[2][8][4];
    #pragma unroll
    for (int mt = 0; mt < 2; mt++)
        #pragma unroll
        for (int nt = 0; nt < 8; nt++)
            #pragma unroll
            for (int q = 0; q < 4; q++) acc[mt][nt][q] = 0.f;

    #pragma unroll 1
    for (int p = 0; p < 2; p++) {
        const float* A  = p ? A2 : A1;
        const float* Bt = p ? Bt2 : Bt1;
        int lda  = p ? lda2 : lda1;
        int K    = p ? K2 : K1;
        int kpad = p ? kpad2 : kpad1;
        if (K == 0) continue;
        int nch = (K + KC - 1) / KC;

        #pragma unroll 1
        for (int c = 0; c < nch; c++) {
            int k0 = c * KC;
            __syncthreads();
            // stage A chunk: 128 rows x 32 k  (1024 float4s / 256 threads)
            #pragma unroll
            for (int i = 0; i < 4; i++) {
                int idx = tid + i * 256;
                int r = idx >> 3, f4 = idx & 7;
                int gr = row0 + r, gk = k0 + f4 * 4;
                float4 v = make_float4(0.f, 0.f, 0.f, 0.f);
                if (gr < M && gk < K)
                    v = *reinterpret_cast<const float4*>(A + (size_t)gr * lda + gk);
                uint4 t; t.x = f2tf32(v.x); t.y = f2tf32(v.y); t.z = f2tf32(v.z); t.w = f2tf32(v.w);
                *reinterpret_cast<uint4*>(&As[r * KPADS + f4 * 4]) = t;
            }
            // stage B chunk: 128 n-rows x 32 k (pre-padded source, always valid)
            #pragma unroll
            for (int i = 0; i < 4; i++) {
                int idx = tid + i * 256;
                int r = idx >> 3, f4 = idx & 7;
                float4 v = *reinterpret_cast<const float4*>(Bt + (size_t)r * kpad + k0 + f4 * 4);
                uint4 t; t.x = f2tf32(v.x); t.y = f2tf32(v.y); t.z = f2tf32(v.z); t.w = f2tf32(v.w);
                *reinterpret_cast<uint4*>(&Bs[r * KPADS + f4 * 4]) = t;
            }
            __syncthreads();

            #pragma unroll
            for (int ks = 0; ks < KC / 8; ks++) {
                int kk = ks * 8;
                // A fragments: 2 m16 tiles
                uint32_t afr[2][4];
                #pragma unroll
                for (int mt = 0; mt < 2; mt++) {
                    int m0 = wm * 32 + mt * 16;
                    afr[mt][0] = As[(m0 + g)     * KPADS + kk + tq];
                    afr[mt][1] = As[(m0 + g + 8) * KPADS + kk + tq];
                    afr[mt][2] = As[(m0 + g)     * KPADS + kk + tq + 4];
                    afr[mt][3] = As[(m0 + g + 8) * KPADS + kk + tq + 4];
                }
                // B fragments: 8 n8 tiles
                uint32_t bfr[8][2];
                #pragma unroll
                for (int nt = 0; nt < 8; nt++) {
                    int n0 = wn * 64 + nt * 8;
                    bfr[nt][0] = Bs[(n0 + g) * KPADS + kk + tq];
                    bfr[nt][1] = Bs[(n0 + g) * KPADS + kk + tq + 4];
                }
                #pragma unroll
                for (int mt = 0; mt < 2; mt++)
                    #pragma unroll
                    for (int nt = 0; nt < 8; nt++) {
                        asm volatile(
                            "mma.sync.aligned.m16n8k8.row.col.f32.tf32.tf32.f32 "
                            "{%0,%1,%2,%3}, {%4,%5,%6,%7}, {%8,%9}, {%0,%1,%2,%3};"
                            : "+f"(acc[mt][nt][0]), "+f"(acc[mt][nt][1]),
                              "+f"(acc[mt][nt][2]), "+f"(acc[mt][nt][3])
                            : "r"(afr[mt][0]), "r"(afr[mt][1]), "r"(afr[mt][2]), "r"(afr[mt][3]),
                              "r"(bfr[nt][0]), "r"(bfr[nt][1]));
                    }
            }
        }
    }

    // epilogue: c0/c1 -> (row = m0+g, cols n0+2tq, +1); c2/c3 -> row+8
    #pragma unroll
    for (int mt = 0; mt < 2; mt++) {
        int r1 = row0 + wm * 32 + mt * 16 + g;
        int r2 = r1 + 8;
        #pragma unroll
        for (int nt = 0; nt < 8; nt++) {
            int col = wn * 64 + nt * 8 + tq * 2;
            float b0 = sbias[col], b1 = sbias[col + 1];
            float2 v1 = make_float2(acc[mt][nt][0] + b0, acc[mt][nt][1] + b1);
            float2 v2 = make_float2(acc[mt][nt][2] + b0, acc[mt][nt][3] + b1);
            if (do_relu) {
                v1.x = fmaxf(v1.x, 0.f); v1.y = fmaxf(v1.y, 0.f);
                v2.x = fmaxf(v2.x, 0.f); v2.y = fmaxf(v2.y, 0.f);
            }
            if (r1 < M) *reinterpret_cast<float2*>(C + (size_t)r1 * 128 + col) = v1;
            if (r2 < M) *reinterpret_cast<float2*>(C + (size_t)r2 * 128 + col) = v2;
        }
    }
}

// ---------------- 8) classifier tail: out[NT,16] = T[NT,128] @ Wc2[128,16] + bc2 ----------------
__global__ __launch_bounds__(256)
void cls_kernel(const float* __restrict__ T, const float* __restrict__ W,
                const float* __restrict__ b, float* __restrict__ out) {
    __shared__ float sW[HID * NCLS];
    __shared__ float sb2[NCLS];
    for (int i = threadIdx.x; i < HID * NCLS; i += 256) sW[i] = W[i];
    if (threadIdx.x < NCLS) sb2[threadIdx.x] = b[threadIdx.x];
    __syncthreads();

    int row = blockIdx.x * 16 + (threadIdx.x >> 4);
    int col = threadIdx.x & 15;
    if (row >= NT) return;

    float s = sb2[col];
    const float4* tp = reinterpret_cast<const float4*>(T + (size_t)row * HID);
    #pragma unroll 8
    for (int k4 = 0; k4 < 32; k4++) {
        float4 v = tp[k4];
        int k = k4 * 4;
        s = fmaf(v.x, sW[(k + 0) * NCLS + col], s);
        s = fmaf(v.y, sW[(k + 1) * NCLS + col], s);
        s = fmaf(v.z, sW[(k + 2) * NCLS + col], s);
        s = fmaf(v.w, sW[(k + 3) * NCLS + col], s);
    }
    out[(size_t)row * NCLS + col] = s;
}

// ---------------- launcher ----------------
extern "C" void kernel_launch(void* const* d_in, const int* in_sizes, int n_in,
                              void* d_out, int out_size) {
    const float* gene  = (const float*)d_in[0];
    const float* train = (const float*)d_in[1];
    const int*   esrc  = (const int*)d_in[2];
    const int*   edst  = (const int*)d_in[3];
    const float* W1n   = (const float*)d_in[4];
    const float* W1s   = (const float*)d_in[5];
    const float* b1    = (const float*)d_in[6];
    const float* W2n   = (const float*)d_in[7];
    const float* W2s   = (const float*)d_in[8];
    const float* b2    = (const float*)d_in[9];
    const float* Wc1   = (const float*)d_in[10];
    const float* bc1   = (const float*)d_in[11];
    const float* Wc2   = (const float*)d_in[12];
    const float* bc2   = (const float*)d_in[13];
    float* out = (float*)d_out;

    float *agg, *h1, *h2, *t, *bt1s, *bt1n, *bt2s, *bt2n, *btc1;
    cudaGetSymbolAddress((void**)&agg,  g_agg);
    cudaGetSymbolAddress((void**)&h1,   g_h1);
    cudaGetSymbolAddress((void**)&h2,   g_h2);
    cudaGetSymbolAddress((void**)&t,    g_t);
    cudaGetSymbolAddress((void**)&bt1s, g_Bt1s);
    cudaGetSymbolAddress((void**)&bt1n, g_Bt1n);
    cudaGetSymbolAddress((void**)&bt2s, g_Bt2s);
    cudaGetSymbolAddress((void**)&bt2n, g_Bt2n);
    cudaGetSymbolAddress((void**)&btc1, g_Btc1);

    zero_kernel<<<(NT + 255) / 256, 256>>>();
    hist_kernel<<<(NE + 255) / 256, 256>>>(edst);
    scan_kernel<<<1, 1024>>>();
    scatter_kernel<<<(NE + 255) / 256, 256>>>(esrc, edst);
    {
        dim3 g((128 * 512 + 255) / 256, 5);
        transw_kernel<<<g, 256>>>(W1s, W1n, W2s, W2n, Wc1);
    }
    agg_kernel<<<(NT + 7) / 8, 256>>>(gene);

    int gblk = (NT + 127) / 128;  // 157
    // h1 = relu(train @ W1_self + agg @ W1_neigh + b1)
    mma_gemm_dual<<<gblk, 256>>>(train, DSTD, DSTD, bt1s, 512,
                                 agg, HID, HID, bt1n, 128, b1, h1, NT, 1);
    // h2 = relu(h1 @ W2_self + agg @ W2_neigh + b2)
    mma_gemm_dual<<<gblk, 256>>>(h1, HID, HID, bt2s, 128,
                                 agg, HID, HID, bt2n, 128, b2, h2, NT, 1);
    // t = relu(h2 @ Wc1 + bc1)
    mma_gemm_dual<<<gblk, 256>>>(h2, OUTD, OUTD, btc1, 128,
                                 nullptr, 0, 0, nullptr, 128, bc1, t, NT, 1);
    // out = t @ Wc2 + bc2
    cls_kernel<<<(NT + 15) / 16, 256>>>(t, Wc2, bc2, out);
}

// round 9
// speedup vs baseline: 2.5478x; 1.0679x over previous
#include <cuda_runtime.h>
#include <cuda_fp16.h>
#include <cstdint>

#define NG 2500
#define NT 20000
#define NE 640000
#define SRCD 128
#define DSTD 500
#define HID 128
#define OUTD 128
#define NCLS 16

// ---------------- scratch (device globals; no allocation allowed) ----------------
__device__ int    g_cnt[NT];
__device__ int    g_rowstart[NT];
__device__ int    g_pos[NE];
__device__ int    g_sorted[NE];
__device__ float  g_agg[(size_t)NT * HID];
__device__ float  g_h1 [(size_t)NT * HID];
__device__ float  g_h2 [(size_t)NT * OUTD];
__device__ __half g_gene16[NG * SRCD];
// transposed weights, [N=128, Kpad] K-major, zero-padded
__device__ float g_Bt1s[128 * 512];
__device__ float g_Bt1n[128 * 128];
__device__ float g_Bt2s[128 * 128];
__device__ float g_Bt2n[128 * 128];
__device__ float g_Btc1[128 * 128];

__device__ __forceinline__ uint32_t f2tf32(float f) {
    uint32_t u;
    asm("cvt.rna.tf32.f32 %0, %1;" : "=r"(u) : "f"(f));
    return u;
}
__device__ __forceinline__ uint32_t smem_to_u32(const void* p) {
    uint32_t a;
    asm("{ .reg .u64 t; cvta.to.shared.u64 t, %1; cvt.u32.u64 %0, t; }" : "=r"(a) : "l"(p));
    return a;
}

// ---------------- 1) fused prep: weight transposes + zero cnt + fp16 gene cache ----------
__global__ void prep_kernel(const float* __restrict__ gene,
                            const float* __restrict__ W1s, const float* __restrict__ W1n,
                            const float* __restrict__ W2s, const float* __restrict__ W2n,
                            const float* __restrict__ Wc1) {
    int m = blockIdx.y;
    int i = blockIdx.x * 256 + threadIdx.x;
    if (m < 5) {
        const float* src; float* dst; int K, Kpad;
        if      (m == 0) { src = W1s; dst = g_Bt1s; K = DSTD; Kpad = 512; }
        else if (m == 1) { src = W1n; dst = g_Bt1n; K = HID;  Kpad = 128; }
        else if (m == 2) { src = W2s; dst = g_Bt2s; K = HID;  Kpad = 128; }
        else if (m == 3) { src = W2n; dst = g_Bt2n; K = HID;  Kpad = 128; }
        else             { src = Wc1; dst = g_Btc1; K = OUTD; Kpad = 128; }
        if (i < 128 * Kpad) {
            int n = i / Kpad, k = i % Kpad;
            dst[i] = (k < K) ? src[k * 128 + n] : 0.f;
        }
    } else if (m == 5) {
        // gene -> fp16, 4 elems per thread via float4
        if (i < NG * SRCD / 4) {
            float4 v = reinterpret_cast<const float4*>(gene)[i];
            __half2 h0 = __floats2half2_rn(v.x, v.y);
            __half2 h1 = __floats2half2_rn(v.z, v.w);
            uint2 u;
            u.x = *reinterpret_cast<uint32_t*>(&h0);
            u.y = *reinterpret_cast<uint32_t*>(&h1);
            reinterpret_cast<uint2*>(g_gene16)[i] = u;
        }
    } else {
        if (i < NT) g_cnt[i] = 0;
    }
}

// ---------------- 2) histogram + within-row rank (ILP 4) ----------------
__global__ void hist_kernel(const int* __restrict__ edst) {
    int base = blockIdx.x * 1024 + threadIdx.x;     // grid 625 * 1024 = NE exactly
    int d0 = edst[base];
    int d1 = edst[base + 256];
    int d2 = edst[base + 512];
    int d3 = edst[base + 768];
    g_pos[base      ] = atomicAdd(&g_cnt[d0], 1);
    g_pos[base + 256] = atomicAdd(&g_cnt[d1], 1);
    g_pos[base + 512] = atomicAdd(&g_cnt[d2], 1);
    g_pos[base + 768] = atomicAdd(&g_cnt[d3], 1);
}

// ---------------- 3) exclusive scan, shuffle-based, 1 block ----------------
__global__ __launch_bounds__(1024) void scan_kernel() {
    __shared__ int wsum[32];
    int t = threadIdx.x, lane = t & 31, w = t >> 5;
    const int L = 20;
    int local[L];
    int s = 0;
    if (t < 1000) {
        int base = t * L;
        #pragma unroll
        for (int j = 0; j < L; j++) { local[j] = s; s += g_cnt[base + j]; }
    }
    int incl = s;
    #pragma unroll
    for (int d = 1; d < 32; d <<= 1) {
        int x = __shfl_up_sync(0xFFFFFFFFu, incl, d);
        if (lane >= d) incl += x;
    }
    if (lane == 31) wsum[w] = incl;
    __syncthreads();
    if (w == 0) {
        int v = wsum[lane];
        #pragma unroll
        for (int d = 1; d < 32; d <<= 1) {
            int x = __shfl_up_sync(0xFFFFFFFFu, v, d);
            if (lane >= d) v += x;
        }
        wsum[lane] = v;
    }
    __syncthreads();
    int off = (w > 0 ? wsum[w - 1] : 0) + incl - s;
    if (t < 1000) {
        int base = t * L;
        #pragma unroll
        for (int j = 0; j < L; j++) g_rowstart[base + j] = off + local[j];
    }
}

// ---------------- 4) pure scatter (no atomics, ILP 4) ----------------
__global__ void scatter_kernel(const int* __restrict__ esrc, const int* __restrict__ edst) {
    int base = blockIdx.x * 1024 + threadIdx.x;
    int d0 = edst[base],       d1 = edst[base + 256];
    int d2 = edst[base + 512], d3 = edst[base + 768];
    int p0 = g_pos[base],       p1 = g_pos[base + 256];
    int p2 = g_pos[base + 512], p3 = g_pos[base + 768];
    int s0 = esrc[base],       s1 = esrc[base + 256];
    int s2 = esrc[base + 512], s3 = esrc[base + 768];
    int r0 = g_rowstart[d0], r1 = g_rowstart[d1];
    int r2 = g_rowstart[d2], r3 = g_rowstart[d3];
    g_sorted[r0 + p0] = s0;
    g_sorted[r1 + p1] = s1;
    g_sorted[r2 + p2] = s2;
    g_sorted[r3 + p3] = s3;
}

// ---------------- 5) mean aggregation from fp16 gene cache: one warp per dst ----------------
__global__ void agg_kernel() {
    int d = blockIdx.x * 8 + (threadIdx.x >> 5);
    if (d >= NT) return;
    int lane = threadIdx.x & 31;
    int start = g_rowstart[d];
    int n = g_cnt[d];
    const uint2* G = reinterpret_cast<const uint2*>(g_gene16);  // 32 uint2 per row

    float4 a0 = {0.f, 0.f, 0.f, 0.f}, a1 = a0, a2 = a0, a3 = a0;
    int e = 0;
    for (; e + 4 <= n; e += 4) {
        int s0 = g_sorted[start + e + 0];
        int s1 = g_sorted[start + e + 1];
        int s2 = g_sorted[start + e + 2];
        int s3 = g_sorted[start + e + 3];
        uint2 u0 = G[s0 * 32 + lane];
        uint2 u1 = G[s1 * 32 + lane];
        uint2 u2 = G[s2 * 32 + lane];
        uint2 u3 = G[s3 * 32 + lane];
        float2 f;
        f = __half22float2(*reinterpret_cast<__half2*>(&u0.x)); a0.x += f.x; a0.y += f.y;
        f = __half22float2(*reinterpret_cast<__half2*>(&u0.y)); a0.z += f.x; a0.w += f.y;
        f = __half22float2(*reinterpret_cast<__half2*>(&u1.x)); a1.x += f.x; a1.y += f.y;
        f = __half22float2(*reinterpret_cast<__half2*>(&u1.y)); a1.z += f.x; a1.w += f.y;
        f = __half22float2(*reinterpret_cast<__half2*>(&u2.x)); a2.x += f.x; a2.y += f.y;
        f = __half22float2(*reinterpret_cast<__half2*>(&u2.y)); a2.z += f.x; a2.w += f.y;
        f = __half22float2(*reinterpret_cast<__half2*>(&u3.x)); a3.x += f.x; a3.y += f.y;
        f = __half22float2(*reinterpret_cast<__half2*>(&u3.y)); a3.z += f.x; a3.w += f.y;
    }
    for (; e < n; e++) {
        int s = g_sorted[start + e];
        uint2 u = G[s * 32 + lane];
        float2 f;
        f = __half22float2(*reinterpret_cast<__half2*>(&u.x)); a0.x += f.x; a0.y += f.y;
        f = __half22float2(*reinterpret_cast<__half2*>(&u.y)); a0.z += f.x; a0.w += f.y;
    }
    float4 acc;
    acc.x = a0.x + a1.x + a2.x + a3.x;
    acc.y = a0.y + a1.y + a2.y + a3.y;
    acc.z = a0.z + a1.z + a2.z + a3.z;
    acc.w = a0.w + a1.w + a2.w + a3.w;
    float inv = 1.0f / fmaxf((float)n, 1.0f);
    acc.x *= inv; acc.y *= inv; acc.z *= inv; acc.w *= inv;
    reinterpret_cast<float4*>(g_agg)[(size_t)d * 32 + lane] = acc;
}

// ---------------- 6) mma.sync tf32 dual GEMM, cp.async double-buffered ----------------
// Block tile 128x128, 8 warps (4M x 2N), warp tile 32x64. Optional fused classifier.
#define KC    32
#define KPADS 36
#define ABUF  (128 * KPADS)               // floats per buffer
// dynamic smem layout (floats):
//   As: 2*ABUF  Bs: 2*ABUF  sbias: 128  sW2: 2048  sb2: 16
#define SM_BS    (2 * ABUF)
#define SM_BIAS  (4 * ABUF)
#define SM_W2    (SM_BIAS + 128)
#define SM_B2    (SM_W2 + 2048)
#define SM_TOTAL ((SM_B2 + 16) * 4)       // bytes
#define TSTRIDE  130

__global__ __launch_bounds__(256, 2)
void mma_gemm_dual(const float* __restrict__ A1, int lda1, int K1, const float* __restrict__ Bt1, int kpad1,
                   const float* __restrict__ A2, int lda2, int K2, const float* __restrict__ Bt2, int kpad2,
                   const float* __restrict__ bias, float* __restrict__ C, int M, int do_relu,
                   const float* __restrict__ Wc2, const float* __restrict__ bc2,
                   float* __restrict__ outp, int fuse_cls) {
    extern __shared__ float smem[];
    float* As    = smem;
    float* Bs    = smem + SM_BS;
    float* sbias = smem + SM_BIAS;

    int tid = threadIdx.x;
    int wid = tid >> 5, lane = tid & 31;
    int wm = wid & 3, wn = wid >> 2;
    int g  = lane >> 2, tq = lane & 3;
    int row0 = blockIdx.x * 128;

    if (tid < 128) sbias[tid] = bias[tid];

    int nch1 = (K1 + KC - 1) / KC;
    int nch2 = K2 ? (K2 + KC - 1) / KC : 0;
    int nct  = nch1 + nch2;

    auto stage = [&](int c, int buf) {
        const float* Ap; const float* Bp; int lda, K, kp, k0;
        if (c < nch1) { Ap = A1; Bp = Bt1; lda = lda1; K = K1; kp = kpad1; k0 = c * KC; }
        else          { Ap = A2; Bp = Bt2; lda = lda2; K = K2; kp = kpad2; k0 = (c - nch1) * KC; }
        float* Ad = As + buf * ABUF;
        float* Bd = Bs + buf * ABUF;
        #pragma unroll
        for (int i = 0; i < 4; i++) {
            int idx = tid + i * 256;
            int r = idx >> 3, f4 = idx & 7;
            int gr = row0 + r, gk = k0 + f4 * 4;
            int ok = (gr < M && gk < K);
            const float* src = Ap + (ok ? ((size_t)gr * lda + gk) : 0);
            uint32_t da = smem_to_u32(Ad + r * KPADS + f4 * 4);
            int sz = ok ? 16 : 0;
            asm volatile("cp.async.cg.shared.global [%0], [%1], 16, %2;"
                         :: "r"(da), "l"(src), "r"(sz));
            const float* bsrc = Bp + (size_t)r * kp + k0 + f4 * 4;
            uint32_t db = smem_to_u32(Bd + r * KPADS + f4 * 4);
            asm volatile("cp.async.cg.shared.global [%0], [%1], 16, %2;"
                         :: "r"(db), "l"(bsrc), "r"(16));
        }
        asm volatile("cp.async.commit_group;" ::: "memory");
    };

    float acc[2][8][4];
    #pragma unroll
    for (int mt = 0; mt < 2; mt++)
        #pragma unroll
        for (int nt = 0; nt < 8; nt++)
            #pragma unroll
            for (int q = 0; q < 4; q++) acc[mt][nt][q] = 0.f;

    stage(0, 0);

    #pragma unroll 1
    for (int c = 0; c < nct; c++) {
        int buf = c & 1;
        if (c + 1 < nct) {
            stage(c + 1, buf ^ 1);
            asm volatile("cp.async.wait_group 1;" ::: "memory");
        } else {
            asm volatile("cp.async.wait_group 0;" ::: "memory");
        }
        __syncthreads();

        const float* Ab = As + buf * ABUF;
        const float* Bb = Bs + buf * ABUF;
        #pragma unroll
        for (int ks = 0; ks < KC / 8; ks++) {
            int kk = ks * 8;
            uint32_t afr[2][4];
            #pragma unroll
            for (int mt = 0; mt < 2; mt++) {
                int m0 = wm * 32 + mt * 16;
                afr[mt][0] = f2tf32(Ab[(m0 + g)     * KPADS + kk + tq]);
                afr[mt][1] = f2tf32(Ab[(m0 + g + 8) * KPADS + kk + tq]);
                afr[mt][2] = f2tf32(Ab[(m0 + g)     * KPADS + kk + tq + 4]);
                afr[mt][3] = f2tf32(Ab[(m0 + g + 8) * KPADS + kk + tq + 4]);
            }
            uint32_t bfr[8][2];
            #pragma unroll
            for (int nt = 0; nt < 8; nt++) {
                int n0 = wn * 64 + nt * 8;
                bfr[nt][0] = f2tf32(Bb[(n0 + g) * KPADS + kk + tq]);
                bfr[nt][1] = f2tf32(Bb[(n0 + g) * KPADS + kk + tq + 4]);
            }
            #pragma unroll
            for (int mt = 0; mt < 2; mt++)
                #pragma unroll
                for (int nt = 0; nt < 8; nt++) {
                    asm volatile(
                        "mma.sync.aligned.m16n8k8.row.col.f32.tf32.tf32.f32 "
                        "{%0,%1,%2,%3}, {%4,%5,%6,%7}, {%8,%9}, {%0,%1,%2,%3};"
                        : "+f"(acc[mt][nt][0]), "+f"(acc[mt][nt][1]),
                          "+f"(acc[mt][nt][2]), "+f"(acc[mt][nt][3])
                        : "r"(afr[mt][0]), "r"(afr[mt][1]), "r"(afr[mt][2]), "r"(afr[mt][3]),
                          "r"(bfr[nt][0]), "r"(bfr[nt][1]));
                }
        }
        __syncthreads();
    }

    if (!fuse_cls) {
        // epilogue: bias + relu + store to C
        #pragma unroll
        for (int mt = 0; mt < 2; mt++) {
            int r1 = row0 + wm * 32 + mt * 16 + g;
            int r2 = r1 + 8;
            #pragma unroll
            for (int nt = 0; nt < 8; nt++) {
                int col = wn * 64 + nt * 8 + tq * 2;
                float b0 = sbias[col], b1 = sbias[col + 1];
                float2 v1 = make_float2(acc[mt][nt][0] + b0, acc[mt][nt][1] + b1);
                float2 v2 = make_float2(acc[mt][nt][2] + b0, acc[mt][nt][3] + b1);
                if (do_relu) {
                    v1.x = fmaxf(v1.x, 0.f); v1.y = fmaxf(v1.y, 0.f);
                    v2.x = fmaxf(v2.x, 0.f); v2.y = fmaxf(v2.y, 0.f);
                }
                if (r1 < M) *reinterpret_cast<float2*>(C + (size_t)r1 * 128 + col) = v1;
                if (r2 < M) *reinterpret_cast<float2*>(C + (size_t)r2 * 128 + col) = v2;
            }
        }
    } else {
        // fused classifier: t tile -> smem, then out = t @ Wc2 + bc2
        float* tS  = smem;               // 128 x TSTRIDE, overlays As/Bs
        float* sW2 = smem + SM_W2;
        float* sb2 = smem + SM_B2;
        for (int i = tid; i < 128 * NCLS; i += 256) sW2[i] = Wc2[i];
        if (tid < NCLS) sb2[tid] = bc2[tid];
        #pragma unroll
        for (int mt = 0; mt < 2; mt++) {
            int lr1 = wm * 32 + mt * 16 + g;
            int lr2 = lr1 + 8;
            #pragma unroll
            for (int nt = 0; nt < 8; nt++) {
                int col = wn * 64 + nt * 8 + tq * 2;
                float b0 = sbias[col], b1 = sbias[col + 1];
                float v10 = fmaxf(acc[mt][nt][0] + b0, 0.f);
                float v11 = fmaxf(acc[mt][nt][1] + b1, 0.f);
                float v20 = fmaxf(acc[mt][nt][2] + b0, 0.f);
                float v21 = fmaxf(acc[mt][nt][3] + b1, 0.f);
                tS[lr1 * TSTRIDE + col]     = v10;
                tS[lr1 * TSTRIDE + col + 1] = v11;
                tS[lr2 * TSTRIDE + col]     = v20;
                tS[lr2 * TSTRIDE + col + 1] = v21;
            }
        }
        __syncthreads();
        int lrow = tid >> 1;
        int cg = (tid & 1) * 8;
        int grow = row0 + lrow;
        if (grow < M) {
            float s[8];
            #pragma unroll
            for (int j = 0; j < 8; j++) s[j] = sb2[cg + j];
            #pragma unroll 4
            for (int k = 0; k < 128; k++) {
                float tv = tS[lrow * TSTRIDE + k];
                float4 w0 = *reinterpret_cast<const float4*>(&sW2[k * NCLS + cg]);
                float4 w1 = *reinterpret_cast<const float4*>(&sW2[k * NCLS + cg + 4]);
                s[0] = fmaf(tv, w0.x, s[0]); s[1] = fmaf(tv, w0.y, s[1]);
                s[2] = fmaf(tv, w0.z, s[2]); s[3] = fmaf(tv, w0.w, s[3]);
                s[4] = fmaf(tv, w1.x, s[4]); s[5] = fmaf(tv, w1.y, s[5]);
                s[6] = fmaf(tv, w1.z, s[6]); s[7] = fmaf(tv, w1.w, s[7]);
            }
            float4 o0 = make_float4(s[0], s[1], s[2], s[3]);
            float4 o1 = make_float4(s[4], s[5], s[6], s[7]);
            *reinterpret_cast<float4*>(outp + (size_t)grow * NCLS + cg)     = o0;
            *reinterpret_cast<float4*>(outp + (size_t)grow * NCLS + cg + 4) = o1;
        }
    }
}

// ---------------- launcher ----------------
extern "C" void kernel_launch(void* const* d_in, const int* in_sizes, int n_in,
                              void* d_out, int out_size) {
    const float* gene  = (const float*)d_in[0];
    const float* train = (const float*)d_in[1];
    const int*   esrc  = (const int*)d_in[2];
    const int*   edst  = (const int*)d_in[3];
    const float* W1n   = (const float*)d_in[4];
    const float* W1s   = (const float*)d_in[5];
    const float* b1    = (const float*)d_in[6];
    const float* W2n   = (const float*)d_in[7];
    const float* W2s   = (const float*)d_in[8];
    const float* b2    = (const float*)d_in[9];
    const float* Wc1   = (const float*)d_in[10];
    const float* bc1   = (const float*)d_in[11];
    const float* Wc2   = (const float*)d_in[12];
    const float* bc2   = (const float*)d_in[13];
    float* out = (float*)d_out;

    float *agg, *h1, *h2, *bt1s, *bt1n, *bt2s, *bt2n, *btc1;
    cudaGetSymbolAddress((void**)&agg,  g_agg);
    cudaGetSymbolAddress((void**)&h1,   g_h1);
    cudaGetSymbolAddress((void**)&h2,   g_h2);
    cudaGetSymbolAddress((void**)&bt1s, g_Bt1s);
    cudaGetSymbolAddress((void**)&bt1n, g_Bt1n);
    cudaGetSymbolAddress((void**)&bt2s, g_Bt2s);
    cudaGetSymbolAddress((void**)&bt2n, g_Bt2n);
    cudaGetSymbolAddress((void**)&btc1, g_Btc1);

    static int smem_set = 0;
    if (!smem_set) {
        cudaFuncSetAttribute(mma_gemm_dual, cudaFuncAttributeMaxDynamicSharedMemorySize, SM_TOTAL);
        smem_set = 1;
    }

    {
        dim3 gp(320, 7);
        prep_kernel<<<gp, 256>>>(gene, W1s, W1n, W2s, W2n, Wc1);
    }
    hist_kernel<<<NE / 1024, 256>>>(edst);
    scan_kernel<<<1, 1024>>>();
    scatter_kernel<<<NE / 1024, 256>>>(esrc, edst);
    agg_kernel<<<(NT + 7) / 8, 256>>>();

    int gblk = (NT + 127) / 128;  // 157
    // h1 = relu(train @ W1_self + agg @ W1_neigh + b1)
    mma_gemm_dual<<<gblk, 256, SM_TOTAL>>>(train, DSTD, DSTD, bt1s, 512,
                                           agg, HID, HID, bt1n, 128, b1, h1, NT, 1,
                                           nullptr, nullptr, nullptr, 0);
    // h2 = relu(h1 @ W2_self + agg @ W2_neigh + b2)
    mma_gemm_dual<<<gblk, 256, SM_TOTAL>>>(h1, HID, HID, bt2s, 128,
                                           agg, HID, HID, bt2n, 128, b2, h2, NT, 1,
                                           nullptr, nullptr, nullptr, 0);
    // out = relu(h2 @ Wc1 + bc1) @ Wc2 + bc2   (fused classifier)
    mma_gemm_dual<<<gblk, 256, SM_TOTAL>>>(h2, OUTD, OUTD, btc1, 128,
                                           nullptr, 0, 0, nullptr, 128, bc1, nullptr, NT, 1,
                                           Wc2, bc2, out, 1);
}

// round 10
// speedup vs baseline: 2.9521x; 1.1587x over previous
#include <cuda_runtime.h>
#include <cuda_fp16.h>
#include <cstdint>

#define NG 2500
#define NT 20000
#define NE 640000
#define SRCD 128
#define DSTD 500
#define HID 128
#define OUTD 128
#define NCLS 16
#define KP1 512               // padded K for layer-1 self GEMM

// ---------------- scratch (device globals; no allocation allowed) ----------------
__device__ int    g_cnt[NT];
__device__ int    g_rowstart[NT];
__device__ int    g_pos[NE];
__device__ int    g_sorted[NE];
__device__ __half g_train16[(size_t)NT * KP1];
__device__ __half g_gene16[NG * SRCD];
__device__ __half g_agg16[(size_t)NT * HID];
__device__ __half g_h1[(size_t)NT * HID];
__device__ __half g_h2[(size_t)NT * OUTD];
// transposed weights, [N=128, Kpad] K-major, fp16, zero-padded
__device__ __half g_Bt1s[128 * KP1];
__device__ __half g_Bt1n[128 * 128];
__device__ __half g_Bt2s[128 * 128];
__device__ __half g_Bt2n[128 * 128];
__device__ __half g_Btc1[128 * 128];

__device__ __forceinline__ uint32_t smem_to_u32(const void* p) {
    uint32_t a;
    asm("{ .reg .u64 t; cvta.to.shared.u64 t, %1; cvt.u32.u64 %0, t; }" : "=r"(a) : "l"(p));
    return a;
}
__device__ __forceinline__ uint32_t h2u(__half2 h) { return *reinterpret_cast<uint32_t*>(&h); }

// ---------------- 1) fused prep (grid-stride tasks) ----------------
__global__ void prep_kernel(const float* __restrict__ gene, const float* __restrict__ train,
                            const float* __restrict__ W1s, const float* __restrict__ W1n,
                            const float* __restrict__ W2s, const float* __restrict__ W2n,
                            const float* __restrict__ Wc1) {
    int task = blockIdx.y;
    int stride = gridDim.x * blockDim.x;
    int t0 = blockIdx.x * blockDim.x + threadIdx.x;
    if (task < 5) {
        const float* src; __half* dst; int K, Kpad;
        if      (task == 0) { src = W1s; dst = g_Bt1s; K = DSTD; Kpad = KP1; }
        else if (task == 1) { src = W1n; dst = g_Bt1n; K = HID;  Kpad = 128; }
        else if (task == 2) { src = W2s; dst = g_Bt2s; K = HID;  Kpad = 128; }
        else if (task == 3) { src = W2n; dst = g_Bt2n; K = HID;  Kpad = 128; }
        else                { src = Wc1; dst = g_Btc1; K = OUTD; Kpad = 128; }
        int N = 128 * Kpad;
        for (int i = t0; i < N; i += stride) {
            int n = i / Kpad, k = i % Kpad;
            dst[i] = (k < K) ? __float2half_rn(src[k * 128 + n]) : __half(0.f);
        }
    } else if (task == 5) {
        int N = NG * SRCD / 4;
        for (int i = t0; i < N; i += stride) {
            float4 v = reinterpret_cast<const float4*>(gene)[i];
            uint2 u;
            u.x = h2u(__floats2half2_rn(v.x, v.y));
            u.y = h2u(__floats2half2_rn(v.z, v.w));
            reinterpret_cast<uint2*>(g_gene16)[i] = u;
        }
    } else if (task == 6) {
        for (int i = t0; i < NT; i += stride) g_cnt[i] = 0;
    } else {
        // train [NT,500] fp32 -> [NT,512] fp16 zero-padded, 8 elems/thread
        int N = NT * (KP1 / 8);
        for (int i = t0; i < N; i += stride) {
            int r = i >> 6;
            int k0 = (i & 63) << 3;
            float f[8];
            #pragma unroll
            for (int j = 0; j < 8; j++) {
                int k = k0 + j;
                f[j] = (k < DSTD) ? train[(size_t)r * DSTD + k] : 0.f;
            }
            uint4 u;
            u.x = h2u(__floats2half2_rn(f[0], f[1]));
            u.y = h2u(__floats2half2_rn(f[2], f[3]));
            u.z = h2u(__floats2half2_rn(f[4], f[5]));
            u.w = h2u(__floats2half2_rn(f[6], f[7]));
            *reinterpret_cast<uint4*>(&g_train16[(size_t)r * KP1 + k0]) = u;
        }
    }
}

// ---------------- 2) histogram + within-row rank (ILP 4) ----------------
__global__ void hist_kernel(const int* __restrict__ edst) {
    int base = blockIdx.x * 1024 + threadIdx.x;
    int d0 = edst[base];
    int d1 = edst[base + 256];
    int d2 = edst[base + 512];
    int d3 = edst[base + 768];
    g_pos[base      ] = atomicAdd(&g_cnt[d0], 1);
    g_pos[base + 256] = atomicAdd(&g_cnt[d1], 1);
    g_pos[base + 512] = atomicAdd(&g_cnt[d2], 1);
    g_pos[base + 768] = atomicAdd(&g_cnt[d3], 1);
}

// ---------------- 3) exclusive scan, shuffle-based, 1 block ----------------
__global__ __launch_bounds__(1024) void scan_kernel() {
    __shared__ int wsum[32];
    int t = threadIdx.x, lane = t & 31, w = t >> 5;
    const int L = 20;
    int local[L];
    int s = 0;
    if (t < 1000) {
        int base = t * L;
        #pragma unroll
        for (int j = 0; j < L; j++) { local[j] = s; s += g_cnt[base + j]; }
    }
    int incl = s;
    #pragma unroll
    for (int d = 1; d < 32; d <<= 1) {
        int x = __shfl_up_sync(0xFFFFFFFFu, incl, d);
        if (lane >= d) incl += x;
    }
    if (lane == 31) wsum[w] = incl;
    __syncthreads();
    if (w == 0) {
        int v = wsum[lane];
        #pragma unroll
        for (int d = 1; d < 32; d <<= 1) {
            int x = __shfl_up_sync(0xFFFFFFFFu, v, d);
            if (lane >= d) v += x;
        }
        wsum[lane] = v;
    }
    __syncthreads();
    int off = (w > 0 ? wsum[w - 1] : 0) + incl - s;
    if (t < 1000) {
        int base = t * L;
        #pragma unroll
        for (int j = 0; j < L; j++) g_rowstart[base + j] = off + local[j];
    }
}

// ---------------- 4) pure scatter (no atomics, ILP 4) ----------------
__global__ void scatter_kernel(const int* __restrict__ esrc, const int* __restrict__ edst) {
    int base = blockIdx.x * 1024 + threadIdx.x;
    int d0 = edst[base],       d1 = edst[base + 256];
    int d2 = edst[base + 512], d3 = edst[base + 768];
    int p0 = g_pos[base],       p1 = g_pos[base + 256];
    int p2 = g_pos[base + 512], p3 = g_pos[base + 768];
    int s0 = esrc[base],       s1 = esrc[base + 256];
    int s2 = esrc[base + 512], s3 = esrc[base + 768];
    g_sorted[g_rowstart[d0] + p0] = s0;
    g_sorted[g_rowstart[d1] + p1] = s1;
    g_sorted[g_rowstart[d2] + p2] = s2;
    g_sorted[g_rowstart[d3] + p3] = s3;
}

// ---------------- 5) mean aggregation from fp16 gene cache -> fp16 agg ----------------
__global__ void agg_kernel() {
    int d = blockIdx.x * 8 + (threadIdx.x >> 5);
    if (d >= NT) return;
    int lane = threadIdx.x & 31;
    int start = g_rowstart[d];
    int n = g_cnt[d];
    const uint2* G = reinterpret_cast<const uint2*>(g_gene16);

    float4 a0 = {0.f, 0.f, 0.f, 0.f}, a1 = a0, a2 = a0, a3 = a0;
    int e = 0;
    for (; e + 4 <= n; e += 4) {
        int s0 = g_sorted[start + e + 0];
        int s1 = g_sorted[start + e + 1];
        int s2 = g_sorted[start + e + 2];
        int s3 = g_sorted[start + e + 3];
        uint2 u0 = G[s0 * 32 + lane];
        uint2 u1 = G[s1 * 32 + lane];
        uint2 u2 = G[s2 * 32 + lane];
        uint2 u3 = G[s3 * 32 + lane];
        float2 f;
        f = __half22float2(*reinterpret_cast<__half2*>(&u0.x)); a0.x += f.x; a0.y += f.y;
        f = __half22float2(*reinterpret_cast<__half2*>(&u0.y)); a0.z += f.x; a0.w += f.y;
        f = __half22float2(*reinterpret_cast<__half2*>(&u1.x)); a1.x += f.x; a1.y += f.y;
        f = __half22float2(*reinterpret_cast<__half2*>(&u1.y)); a1.z += f.x; a1.w += f.y;
        f = __half22float2(*reinterpret_cast<__half2*>(&u2.x)); a2.x += f.x; a2.y += f.y;
        f = __half22float2(*reinterpret_cast<__half2*>(&u2.y)); a2.z += f.x; a2.w += f.y;
        f = __half22float2(*reinterpret_cast<__half2*>(&u3.x)); a3.x += f.x; a3.y += f.y;
        f = __half22float2(*reinterpret_cast<__half2*>(&u3.y)); a3.z += f.x; a3.w += f.y;
    }
    for (; e < n; e++) {
        int s = g_sorted[start + e];
        uint2 u = G[s * 32 + lane];
        float2 f;
        f = __half22float2(*reinterpret_cast<__half2*>(&u.x)); a0.x += f.x; a0.y += f.y;
        f = __half22float2(*reinterpret_cast<__half2*>(&u.y)); a0.z += f.x; a0.w += f.y;
    }
    float4 acc;
    acc.x = a0.x + a1.x + a2.x + a3.x;
    acc.y = a0.y + a1.y + a2.y + a3.y;
    acc.z = a0.z + a1.z + a2.z + a3.z;
    acc.w = a0.w + a1.w + a2.w + a3.w;
    float inv = 1.0f / fmaxf((float)n, 1.0f);
    uint2 u;
    u.x = h2u(__floats2half2_rn(acc.x * inv, acc.y * inv));
    u.y = h2u(__floats2half2_rn(acc.z * inv, acc.w * inv));
    reinterpret_cast<uint2*>(g_agg16)[(size_t)d * 32 + lane] = u;
}

// ---------------- 6) fp16 mma.sync dual GEMM (m16n8k16), cp.async double-buffered ----------
// Block tile 128x128, 8 warps (4M x 2N), warp tile 32x64. Optional fused classifier.
#define KC    64                 // k-chunk (halves)
#define KPADH 72                 // smem row stride in halves (bank = 4g+tq, conflict-free)
#define ABUFH (128 * KPADH)      // halves per buffer
// smem: As[2*ABUFH] + Bs[2*ABUFH] halves, then floats: sbias[128], sW2[2048], sb2[16]
#define SM_F0    (ABUFH)         // floats consumed by As+Bs halves: 4*ABUFH*2/4 = 2*ABUFH
#define SM_BIASF (2 * ABUFH)
#define SM_W2F   (SM_BIASF + 128)
#define SM_B2F   (SM_W2F + 2048)
#define SM_TOTAL ((SM_B2F + 16) * 4)
#define TSTRIDE  130

__global__ __launch_bounds__(256, 2)
void mma_gemm_dual(const __half* __restrict__ A1, int lda1, int K1, const __half* __restrict__ Bt1,
                   const __half* __restrict__ A2, int lda2, int K2, const __half* __restrict__ Bt2,
                   const float* __restrict__ bias, __half* __restrict__ C, int M, 
                   const float* __restrict__ Wc2, const float* __restrict__ bc2,
                   float* __restrict__ outp, int fuse_cls) {
    extern __shared__ float smemf[];
    __half* As = reinterpret_cast<__half*>(smemf);
    __half* Bs = As + 2 * ABUFH;
    float* sbias = smemf + SM_BIASF;

    int tid = threadIdx.x;
    int wid = tid >> 5, lane = tid & 31;
    int wm = wid & 3, wn = wid >> 2;
    int g  = lane >> 2, tq = lane & 3;
    int row0 = blockIdx.x * 128;

    if (tid < 128) sbias[tid] = bias[tid];

    int nch1 = K1 / KC;
    int nch2 = K2 / KC;
    int nct  = nch1 + nch2;

    auto stage = [&](int c, int buf) {
        const __half* Ap; const __half* Bp; int lda, kb, k0;
        if (c < nch1) { Ap = A1; Bp = Bt1; lda = lda1; kb = K1; k0 = c * KC; }
        else          { Ap = A2; Bp = Bt2; lda = lda2; kb = K2; k0 = (c - nch1) * KC; }
        __half* Ad = As + buf * ABUFH;
        __half* Bd = Bs + buf * ABUFH;
        #pragma unroll
        for (int i = 0; i < 4; i++) {
            int idx = tid + i * 256;          // 0..1023
            int r = idx >> 3, seg = idx & 7;  // row, 16B segment (8 halves)
            int gr = row0 + r;
            int ok = gr < M;
            const __half* src = Ap + ((size_t)(ok ? gr : 0) * lda + k0 + seg * 8);
            uint32_t da = smem_to_u32(Ad + r * KPADH + seg * 8);
            asm volatile("cp.async.cg.shared.global [%0], [%1], 16, %2;"
                         :: "r"(da), "l"(src), "r"(ok ? 16 : 0));
            const __half* bsrc = Bp + ((size_t)r * kb + k0 + seg * 8);
            uint32_t db = smem_to_u32(Bd + r * KPADH + seg * 8);
            asm volatile("cp.async.cg.shared.global [%0], [%1], 16, %2;"
                         :: "r"(db), "l"(bsrc), "r"(16));
        }
        asm volatile("cp.async.commit_group;" ::: "memory");
    };

    float acc[2][8][4];
    #pragma unroll
    for (int mt = 0; mt < 2; mt++)
        #pragma unroll
        for (int nt = 0; nt < 8; nt++)
            #pragma unroll
            for (int q = 0; q < 4; q++) acc[mt][nt][q] = 0.f;

    stage(0, 0);

    #pragma unroll 1
    for (int c = 0; c < nct; c++) {
        int buf = c & 1;
        if (c + 1 < nct) {
            stage(c + 1, buf ^ 1);
            asm volatile("cp.async.wait_group 1;" ::: "memory");
        } else {
            asm volatile("cp.async.wait_group 0;" ::: "memory");
        }
        __syncthreads();

        const __half* Ab = As + buf * ABUFH;
        const __half* Bb = Bs + buf * ABUFH;
        #pragma unroll
        for (int ks = 0; ks < KC / 16; ks++) {
            int kk = ks * 16;
            uint32_t afr[2][4];
            #pragma unroll
            for (int mt = 0; mt < 2; mt++) {
                int m0 = wm * 32 + mt * 16;
                const __half* ap = Ab + (m0 + g) * KPADH + kk + 2 * tq;
                afr[mt][0] = *reinterpret_cast<const uint32_t*>(ap);
                afr[mt][1] = *reinterpret_cast<const uint32_t*>(ap + 8 * KPADH);
                afr[mt][2] = *reinterpret_cast<const uint32_t*>(ap + 8);
                afr[mt][3] = *reinterpret_cast<const uint32_t*>(ap + 8 * KPADH + 8);
            }
            uint32_t bfr[8][2];
            #pragma unroll
            for (int nt = 0; nt < 8; nt++) {
                int n0 = wn * 64 + nt * 8;
                const __half* bp = Bb + (n0 + g) * KPADH + kk + 2 * tq;
                bfr[nt][0] = *reinterpret_cast<const uint32_t*>(bp);
                bfr[nt][1] = *reinterpret_cast<const uint32_t*>(bp + 8);
            }
            #pragma unroll
            for (int mt = 0; mt < 2; mt++)
                #pragma unroll
                for (int nt = 0; nt < 8; nt++) {
                    asm volatile(
                        "mma.sync.aligned.m16n8k16.row.col.f32.f16.f16.f32 "
                        "{%0,%1,%2,%3}, {%4,%5,%6,%7}, {%8,%9}, {%0,%1,%2,%3};"
                        : "+f"(acc[mt][nt][0]), "+f"(acc[mt][nt][1]),
                          "+f"(acc[mt][nt][2]), "+f"(acc[mt][nt][3])
                        : "r"(afr[mt][0]), "r"(afr[mt][1]), "r"(afr[mt][2]), "r"(afr[mt][3]),
                          "r"(bfr[nt][0]), "r"(bfr[nt][1]));
                }
        }
        __syncthreads();
    }

    if (!fuse_cls) {
        // epilogue: bias + relu + fp16 store
        #pragma unroll
        for (int mt = 0; mt < 2; mt++) {
            int r1 = row0 + wm * 32 + mt * 16 + g;
            int r2 = r1 + 8;
            #pragma unroll
            for (int nt = 0; nt < 8; nt++) {
                int col = wn * 64 + nt * 8 + tq * 2;
                float b0 = sbias[col], b1 = sbias[col + 1];
                float v10 = fmaxf(acc[mt][nt][0] + b0, 0.f);
                float v11 = fmaxf(acc[mt][nt][1] + b1, 0.f);
                float v20 = fmaxf(acc[mt][nt][2] + b0, 0.f);
                float v21 = fmaxf(acc[mt][nt][3] + b1, 0.f);
                if (r1 < M)
                    *reinterpret_cast<uint32_t*>(C + (size_t)r1 * 128 + col) =
                        h2u(__floats2half2_rn(v10, v11));
                if (r2 < M)
                    *reinterpret_cast<uint32_t*>(C + (size_t)r2 * 128 + col) =
                        h2u(__floats2half2_rn(v20, v21));
            }
        }
    } else {
        // fused classifier: t tile (fp32) -> smem, out = t @ Wc2 + bc2
        float* tS  = smemf;               // 128 x TSTRIDE floats, overlays As/Bs
        float* sW2 = smemf + SM_W2F;
        float* sb2 = smemf + SM_B2F;
        for (int i = tid; i < 128 * NCLS; i += 256) sW2[i] = Wc2[i];
        if (tid < NCLS) sb2[tid] = bc2[tid];
        #pragma unroll
        for (int mt = 0; mt < 2; mt++) {
            int lr1 = wm * 32 + mt * 16 + g;
            int lr2 = lr1 + 8;
            #pragma unroll
            for (int nt = 0; nt < 8; nt++) {
                int col = wn * 64 + nt * 8 + tq * 2;
                float b0 = sbias[col], b1 = sbias[col + 1];
                tS[lr1 * TSTRIDE + col]     = fmaxf(acc[mt][nt][0] + b0, 0.f);
                tS[lr1 * TSTRIDE + col + 1] = fmaxf(acc[mt][nt][1] + b1, 0.f);
                tS[lr2 * TSTRIDE + col]     = fmaxf(acc[mt][nt][2] + b0, 0.f);
                tS[lr2 * TSTRIDE + col + 1] = fmaxf(acc[mt][nt][3] + b1, 0.f);
            }
        }
        __syncthreads();
        int lrow = tid >> 1;
        int cg = (tid & 1) * 8;
        int grow = row0 + lrow;
        if (grow < M) {
            float s[8];
            #pragma unroll
            for (int j = 0; j < 8; j++) s[j] = sb2[cg + j];
            #pragma unroll 4
            for (int k = 0; k < 128; k++) {
                float tv = tS[lrow * TSTRIDE + k];
                float4 w0 = *reinterpret_cast<const float4*>(&sW2[k * NCLS + cg]);
                float4 w1 = *reinterpret_cast<const float4*>(&sW2[k * NCLS + cg + 4]);
                s[0] = fmaf(tv, w0.x, s[0]); s[1] = fmaf(tv, w0.y, s[1]);
                s[2] = fmaf(tv, w0.z, s[2]); s[3] = fmaf(tv, w0.w, s[3]);
                s[4] = fmaf(tv, w1.x, s[4]); s[5] = fmaf(tv, w1.y, s[5]);
                s[6] = fmaf(tv, w1.z, s[6]); s[7] = fmaf(tv, w1.w, s[7]);
            }
            *reinterpret_cast<float4*>(outp + (size_t)grow * NCLS + cg) =
                make_float4(s[0], s[1], s[2], s[3]);
            *reinterpret_cast<float4*>(outp + (size_t)grow * NCLS + cg + 4) =
                make_float4(s[4], s[5], s[6], s[7]);
        }
    }
}

// ---------------- launcher ----------------
extern "C" void kernel_launch(void* const* d_in, const int* in_sizes, int n_in,
                              void* d_out, int out_size) {
    const float* gene  = (const float*)d_in[0];
    const float* train = (const float*)d_in[1];
    const int*   esrc  = (const int*)d_in[2];
    const int*   edst  = (const int*)d_in[3];
    const float* W1n   = (const float*)d_in[4];
    const float* W1s   = (const float*)d_in[5];
    const float* b1    = (const float*)d_in[6];
    const float* W2n   = (const float*)d_in[7];
    const float* W2s   = (const float*)d_in[8];
    const float* b2    = (const float*)d_in[9];
    const float* Wc1   = (const float*)d_in[10];
    const float* bc1   = (const float*)d_in[11];
    const float* Wc2   = (const float*)d_in[12];
    const float* bc2   = (const float*)d_in[13];
    float* out = (float*)d_out;

    __half *train16, *agg16, *h1, *h2, *bt1s, *bt1n, *bt2s, *bt2n, *btc1;
    cudaGetSymbolAddress((void**)&train16, g_train16);
    cudaGetSymbolAddress((void**)&agg16,   g_agg16);
    cudaGetSymbolAddress((void**)&h1,      g_h1);
    cudaGetSymbolAddress((void**)&h2,      g_h2);
    cudaGetSymbolAddress((void**)&bt1s,    g_Bt1s);
    cudaGetSymbolAddress((void**)&bt1n,    g_Bt1n);
    cudaGetSymbolAddress((void**)&bt2s,    g_Bt2s);
    cudaGetSymbolAddress((void**)&bt2n,    g_Bt2n);
    cudaGetSymbolAddress((void**)&btc1,    g_Btc1);

    static int smem_set = 0;
    if (!smem_set) {
        cudaFuncSetAttribute(mma_gemm_dual, cudaFuncAttributeMaxDynamicSharedMemorySize, SM_TOTAL);
        smem_set = 1;
    }

    {
        dim3 gp(512, 8);
        prep_kernel<<<gp, 256>>>(gene, train, W1s, W1n, W2s, W2n, Wc1);
    }
    hist_kernel<<<NE / 1024, 256>>>(edst);
    scan_kernel<<<1, 1024>>>();
    scatter_kernel<<<NE / 1024, 256>>>(esrc, edst);
    agg_kernel<<<(NT + 7) / 8, 256>>>();

    int gblk = (NT + 127) / 128;  // 157
    // h1 = relu(train @ W1_self + agg @ W1_neigh + b1)
    mma_gemm_dual<<<gblk, 256, SM_TOTAL>>>(train16, KP1, KP1, bt1s,
                                           agg16, HID, HID, bt1n, b1, h1, NT,
                                           nullptr, nullptr, nullptr, 0);
    // h2 = relu(h1 @ W2_self + agg @ W2_neigh + b2)
    mma_gemm_dual<<<gblk, 256, SM_TOTAL>>>(h1, HID, HID, bt2s,
                                           agg16, HID, HID, bt2n, b2, h2, NT,
                                           nullptr, nullptr, nullptr, 0);
    // out = relu(h2 @ Wc1 + bc1) @ Wc2 + bc2   (fused classifier)
    mma_gemm_dual<<<gblk, 256, SM_TOTAL>>>(h2, HID, HID, btc1,
                                           nullptr, HID, 0, nullptr, bc1, nullptr, NT,
                                           Wc2, bc2, out, 1);
}